// round 14
// baseline (speedup 1.0000x reference)
#include <cuda_runtime.h>
#include <cuda_bf16.h>
#include <cstdint>

// ---------------- problem constants ----------------
#define NN     50000
#define EE     800000
#define HIDN   96
#define GK     128      // fp32 A row stride (x and acat both 128 wide)
#define NODEF  128
#define TEMPF  10

// ---------------- device scratch ----------------
__device__ __align__(16) float g_dinv [NN];
__device__ __align__(16) float g_hs   [NN * HIDN];
__device__ __align__(16) float g_acat [NN * GK];
__device__ __align__(16) float g_xw2  [NN];
__device__ int   g_cnt [NN];
__device__ int   g_row [NN];
__device__ int   g_woff[NN];
__device__ int   g_csr [EE];
// B fragment buffers: [0]=W_gcn, [1]=W1; each 12288 uints (hi 0..6143, lo 6144..12287)
__device__ __align__(16) uint32_t g_bf[2 * 12288];

// ---------------- helpers ----------------
__device__ __forceinline__ uint32_t pack2(float a, float b) {
    __nv_bfloat16 ha = __float2bfloat16_rn(a), hb = __float2bfloat16_rn(b);
    return (uint32_t)__bfloat16_as_ushort(ha) | ((uint32_t)__bfloat16_as_ushort(hb) << 16);
}

__device__ __forceinline__ void split2(float2 f, uint32_t& hi, uint32_t& lo) {
    uint32_t h = pack2(f.x, f.y);
    float hx = __uint_as_float(h << 16);          // low bf16 as f32
    float hy = __uint_as_float(h & 0xFFFF0000u);  // high bf16 as f32
    hi = h;
    lo = pack2(f.x - hx, f.y - hy);
}

// m16n8k8: A reg0 = row g (k pair), reg1 = row g+8; B 1 reg; C 4 regs
__device__ __forceinline__ void mma1688(float* c, uint32_t a0, uint32_t a1, uint32_t b0) {
    asm volatile(
        "mma.sync.aligned.m16n8k8.row.col.f32.bf16.bf16.f32 "
        "{%0,%1,%2,%3}, {%4,%5}, {%6}, {%0,%1,%2,%3};"
        : "+f"(c[0]), "+f"(c[1]), "+f"(c[2]), "+f"(c[3])
        : "r"(a0), "r"(a1), "r"(b0));
}

// pack W[k][n] (HIDN cols) into m16n8k8 fragment order at dst (idx in [0,6144))
__device__ __forceinline__ void pack_one(uint32_t* dst, const float* W, int Ksrc, int idx) {
    int lane = idx & 31, t = idx >> 5;     // t in [0,192)
    int nt = t % 12, kt = t / 12;          // kt in [0,16)
    int g = lane >> 2, tig = lane & 3;
    int n  = nt * 8 + g;
    int k0 = kt * 8 + tig * 2;
    float w0 = (k0     < Ksrc) ? W[(size_t)k0       * HIDN + n] : 0.0f;
    float w1 = (k0 + 1 < Ksrc) ? W[(size_t)(k0 + 1) * HIDN + n] : 0.0f;
    uint32_t hi, lo;
    split2(make_float2(w0, w1), hi, lo);
    dst[idx]        = hi;
    dst[6144 + idx] = lo;
}

// ---------------- init: zero counts + pack BOTH weight matrices (1 launch) ----------
// blocks [0,196): zero g_cnt; [196,220): pack W_gcn -> g_bf[0]; [220,244): W1 -> g_bf[1]
__global__ void __launch_bounds__(256) k_init(const float* __restrict__ W_gcn,
                                              const float* __restrict__ W1, int n) {
    int b = blockIdx.x, tid = threadIdx.x;
    if (b < 196) {
        int i = b * 256 + tid;
        if (i < n) g_cnt[i] = 0;
    } else if (b < 220) {
        pack_one(g_bf, W_gcn, 128, (b - 196) * 256 + tid);
    } else {
        pack_one(g_bf + 12288, W1, HIDN + TEMPF, (b - 220) * 256 + tid);
    }
}

__global__ void k_count(const int* __restrict__ ei, int E) {
    int e = blockIdx.x * blockDim.x + threadIdx.x;
    if (e < E) atomicAdd(&g_cnt[ei[E + e]], 1);
}

// ---------------- single-kernel exclusive scan + cursors + dinv ----------------
// each block: offset = sum of all counts before its window (coalesced), then in-block scan
__global__ void __launch_bounds__(256) k_scan(int n) {
    __shared__ int ws[8];
    __shared__ int sOff;
    int tid = threadIdx.x, lane = tid & 31, w = tid >> 5;
    int base = blockIdx.x * 256;

    // block offset: coalesced strided sum of g_cnt[0 .. base)
    int acc = 0;
    for (int j = tid; j < base; j += 256) acc += g_cnt[j];
#pragma unroll
    for (int o = 16; o; o >>= 1) acc += __shfl_xor_sync(0xffffffffu, acc, o);
    if (lane == 0) ws[w] = acc;
    __syncthreads();
    if (tid == 0) {
        int s = 0;
#pragma unroll
        for (int q = 0; q < 8; q++) s += ws[q];
        sOff = s;
    }
    __syncthreads();

    // in-block exclusive scan of this window
    int i = base + tid;
    int v = (i < n) ? g_cnt[i] : 0;
    int x = v;
#pragma unroll
    for (int o = 1; o < 32; o <<= 1) {
        int y = __shfl_up_sync(0xffffffffu, x, o);
        if (lane >= o) x += y;
    }
    __syncthreads();   // ws reuse
    if (lane == 31) ws[w] = x;
    __syncthreads();
    if (tid < 8) {
        int y = ws[tid];
#pragma unroll
        for (int o = 1; o < 8; o <<= 1) {
            int z = __shfl_up_sync(0xffu, y, o);
            if ((int)tid >= o) y += z;
        }
        ws[tid] = y;
    }
    __syncthreads();
    if (i >= n) return;
    int excl = x - v + (w ? ws[w - 1] : 0) + sOff;
    g_row [i] = excl;
    g_woff[i] = excl;
    g_dinv[i] = rsqrtf((float)(v + 1));   // +1 self loop
}

__global__ void k_fill(const int* __restrict__ ei, int E) {
    int e = blockIdx.x * blockDim.x + threadIdx.x;
    if (e >= E) return;
    int src = ei[e];
    int dst = ei[E + e];
    int pos = atomicAdd(&g_woff[dst], 1);
    g_csr[pos] = src;
}

// ---------------- HMMA GEMM: C[128,96] = A[128x128] @ B (2-way bf16 split) ----------
// mode 0: A=A_ext(x), B=g_bf[0];  g_hs[m]=dinv[m]*C[m]; fused g_xw2[m]=x[m].W2[96:224]
// mode 1: A=g_acat,   B=g_bf[1];  out[m] = relu( relu(C[m]+b1).W2[0:96] + xw2[m] + b2 )
// NOTE: device-side selection of A/B (host cannot pass __device__ symbols!)
__global__ void __launch_bounds__(256) k_mma(
    const float* __restrict__ A_ext,
    const float* __restrict__ b1,
    const float* __restrict__ W2,
    const float* __restrict__ b2,
    float* __restrict__ outp,
    int mode, int M)
{
    __shared__ uint32_t sbf[6144];   // 24 KB static: one k-half (hi at 0, lo at 3072)

    const float* __restrict__ A = (mode == 0) ? A_ext : g_acat;
    const uint32_t* __restrict__ bfp = g_bf + mode * 12288;

    int tid  = threadIdx.x;
    int w    = tid >> 5;
    int lane = tid & 31;
    int g    = lane >> 2;
    int tig  = lane & 3;
    int m0   = blockIdx.x * 128 + w * 16 + g;
    int m1   = m0 + 8;
    bool v0  = m0 < M, v1 = m1 < M;

    float acc[12][4];
#pragma unroll
    for (int nt = 0; nt < 12; nt++)
#pragma unroll
        for (int q = 0; q < 4; q++) acc[nt][q] = 0.0f;

    float px0 = 0.0f, px1 = 0.0f;   // mode 0: partial x.W2[96:224]

    const float* a0p = A + (size_t)m0 * GK;
    const float* a1p = A + (size_t)m1 * GK;

    for (int st = 0; st < 2; st++) {
        __syncthreads();   // previous stage reads done before overwrite
        {
            const uint4* srcH = reinterpret_cast<const uint4*>(bfp + st * 3072);
            const uint4* srcL = reinterpret_cast<const uint4*>(bfp + 6144 + st * 3072);
            uint4* dstH = reinterpret_cast<uint4*>(sbf);
            uint4* dstL = reinterpret_cast<uint4*>(sbf + 3072);
#pragma unroll
            for (int i = tid; i < 768; i += 256) { dstH[i] = srcH[i]; dstL[i] = srcL[i]; }
        }
        __syncthreads();

#pragma unroll
        for (int kl = 0; kl < 8; kl++) {
            int c0 = (st * 8 + kl) * 8 + tig * 2;
            float2 z = make_float2(0.f, 0.f);
            float2 fa = v0 ? *reinterpret_cast<const float2*>(a0p + c0) : z;  // row g
            float2 fb = v1 ? *reinterpret_cast<const float2*>(a1p + c0) : z;  // row g+8
            if (mode == 0) {
                float wa = __ldg(W2 + HIDN + c0);
                float wb = __ldg(W2 + HIDN + c0 + 1);
                px0 = fmaf(fa.x, wa, fmaf(fa.y, wb, px0));
                px1 = fmaf(fb.x, wa, fmaf(fb.y, wb, px1));
            }
            uint32_t ah0, al0, ah1, al1;
            split2(fa, ah0, al0);
            split2(fb, ah1, al1);

            int eb = kl * 384 + lane;
#pragma unroll
            for (int nt = 0; nt < 12; nt++) {
                uint32_t bh = sbf[eb + nt * 32];
                uint32_t bl = sbf[3072 + eb + nt * 32];
                mma1688(acc[nt], ah0, ah1, bh);   // ah*bh
                mma1688(acc[nt], ah0, ah1, bl);   // ah*bl
                mma1688(acc[nt], al0, al1, bh);   // al*bh
            }
        }
    }

    if (mode == 0) {
        float s0 = v0 ? g_dinv[m0] : 0.0f;
        float s1 = v1 ? g_dinv[m1] : 0.0f;
#pragma unroll
        for (int nt = 0; nt < 12; nt++) {
            int col = nt * 8 + tig * 2;
            if (v0) *reinterpret_cast<float2*>(g_hs + (size_t)m0 * HIDN + col) =
                        make_float2(acc[nt][0] * s0, acc[nt][1] * s0);
            if (v1) *reinterpret_cast<float2*>(g_hs + (size_t)m1 * HIDN + col) =
                        make_float2(acc[nt][2] * s1, acc[nt][3] * s1);
        }
        px0 += __shfl_xor_sync(0xffffffffu, px0, 1);
        px0 += __shfl_xor_sync(0xffffffffu, px0, 2);
        px1 += __shfl_xor_sync(0xffffffffu, px1, 1);
        px1 += __shfl_xor_sync(0xffffffffu, px1, 2);
        if (tig == 0) {
            if (v0) g_xw2[m0] = px0;
            if (v1) g_xw2[m1] = px1;
        }
    } else {
        float p0 = 0.0f, p1 = 0.0f;
#pragma unroll
        for (int nt = 0; nt < 12; nt++) {
            int col = nt * 8 + tig * 2;
            float bb0 = __ldg(b1 + col), bb1 = __ldg(b1 + col + 1);
            float ww0 = __ldg(W2 + col), ww1 = __ldg(W2 + col + 1);
            p0 = fmaf(fmaxf(acc[nt][0] + bb0, 0.0f), ww0, p0);
            p0 = fmaf(fmaxf(acc[nt][1] + bb1, 0.0f), ww1, p0);
            p1 = fmaf(fmaxf(acc[nt][2] + bb0, 0.0f), ww0, p1);
            p1 = fmaf(fmaxf(acc[nt][3] + bb1, 0.0f), ww1, p1);
        }
        p0 += __shfl_xor_sync(0xffffffffu, p0, 1);
        p0 += __shfl_xor_sync(0xffffffffu, p0, 2);
        p1 += __shfl_xor_sync(0xffffffffu, p1, 1);
        p1 += __shfl_xor_sync(0xffffffffu, p1, 2);
        if (tig == 0) {
            float b2v = __ldg(b2);
            if (v0) outp[m0] = fmaxf(p0 + g_xw2[m0] + b2v, 0.0f);
            if (v1) outp[m1] = fmaxf(p1 + g_xw2[m1] + b2v, 0.0f);
        }
    }
}

// ---------------- gather segment-sum + fused acat pack (proven) ----------------
__global__ void __launch_bounds__(256) k_gather(
    const float* __restrict__ temporal,
    const float* __restrict__ b_gcn, int n)
{
    int gw   = (blockIdx.x * blockDim.x + threadIdx.x) >> 5;
    int lane = threadIdx.x & 31;
    if (gw >= n) return;
    int i = gw;

    float4 acc = make_float4(0.f, 0.f, 0.f, 0.f);
    if (lane < 24)
        acc = reinterpret_cast<const float4*>(g_hs)[(size_t)i * 24 + lane];  // self loop

    int start = g_row[i];
    int cnt   = g_cnt[i];
    for (int base = 0; base < cnt; base += 32) {
        int e = base + lane;
        int s = (e < cnt) ? g_csr[start + e] : 0;
        int m = min(32, cnt - base);
        int j = 0;
        for (; j + 2 <= m; j += 2) {
            int s0 = __shfl_sync(0xffffffffu, s, j);
            int s1 = __shfl_sync(0xffffffffu, s, j + 1);
            if (lane < 24) {
                float4 v0 = reinterpret_cast<const float4*>(g_hs)[(size_t)s0 * 24 + lane];
                float4 v1 = reinterpret_cast<const float4*>(g_hs)[(size_t)s1 * 24 + lane];
                acc.x += v0.x + v1.x; acc.y += v0.y + v1.y;
                acc.z += v0.z + v1.z; acc.w += v0.w + v1.w;
            }
        }
        if (j < m) {
            int s0 = __shfl_sync(0xffffffffu, s, j);
            if (lane < 24) {
                float4 v0 = reinterpret_cast<const float4*>(g_hs)[(size_t)s0 * 24 + lane];
                acc.x += v0.x; acc.y += v0.y; acc.z += v0.z; acc.w += v0.w;
            }
        }
    }

    float di = g_dinv[i];
    if (lane < 24) {
        float4 b = reinterpret_cast<const float4*>(b_gcn)[lane];
        float4 o;
        o.x = fmaxf(fmaf(di, acc.x, b.x), 0.0f);
        o.y = fmaxf(fmaf(di, acc.y, b.y), 0.0f);
        o.z = fmaxf(fmaf(di, acc.z, b.z), 0.0f);
        o.w = fmaxf(fmaf(di, acc.w, b.w), 0.0f);
        reinterpret_cast<float4*>(g_acat)[(size_t)i * 32 + lane] = o;
    } else {
#pragma unroll
        for (int q = 0; q < 4; q++) {
            int c = 96 + (lane - 24) * 4 + q;
            float v = (c < HIDN + TEMPF) ? temporal[(size_t)i * TEMPF + (c - HIDN)] : 0.0f;
            g_acat[(size_t)i * GK + c] = v;
        }
    }
}

// ---------------- launch ----------------
extern "C" void kernel_launch(void* const* d_in, const int* in_sizes, int n_in,
                              void* d_out, int out_size) {
    const float* x        = (const float*)d_in[0];
    const int*   ei       = (const int*)  d_in[1];   // int32 (JAX x64 disabled)
    const float* temporal = (const float*)d_in[2];
    const float* W_gcn    = (const float*)d_in[3];
    const float* b_gcn    = (const float*)d_in[4];
    const float* W1       = (const float*)d_in[5];
    const float* b1       = (const float*)d_in[6];
    const float* W2       = (const float*)d_in[7];
    const float* b2       = (const float*)d_in[8];
    float*       out      = (float*)d_out;

    int N  = in_sizes[0] / NODEF;   // 50000
    int E  = in_sizes[1] / 2;       // 800000
    int nb = (N + 255) / 256;       // 196
    int ng = (N + 127) / 128;       // 391 HMMA tiles

    k_init  <<<nb + 48, 256>>>(W_gcn, W1, N);        // zero cnt + pack both B
    k_count <<<(E + 255) / 256, 256>>>(ei, E);
    k_scan  <<<nb, 256>>>(N);                        // row/woff/dinv in one kernel
    k_fill  <<<(E + 255) / 256, 256>>>(ei, E);

    // GEMM1: g_hs = dinv * (x @ W_gcn); fused g_xw2 = x . W2[96:224]
    k_mma   <<<ng, 256>>>(x, nullptr, W2, nullptr, nullptr, 0, N);

    k_gather<<<(N * 32 + 255) / 256, 256>>>(temporal, b_gcn, N);   // g_acat

    // GEMM2 + fused final: out = relu(relu(acat@W1+b1).W2[0:96] + xw2 + b2)
    k_mma   <<<ng, 256>>>(nullptr, b1, W2, b2, out, 1, N);
}

// round 15
// speedup vs baseline: 1.0472x; 1.0472x over previous
#include <cuda_runtime.h>
#include <cuda_bf16.h>
#include <cstdint>

// ---------------- problem constants ----------------
#define NN     50000
#define EE     800000
#define HIDN   96
#define GK     128      // fp32 A row stride (x and acat both 128 wide)
#define NODEF  128
#define TEMPF  10

// ---------------- device scratch ----------------
__device__ __align__(16) float g_dinv [NN];
__device__ __align__(16) float g_hs   [NN * HIDN];
__device__ __align__(16) float g_acat [NN * GK];
__device__ __align__(16) float g_xw2  [NN];
__device__ int   g_cnt [NN];
__device__ int   g_row [NN];
__device__ int   g_woff[NN];
__device__ int   g_csr [EE];
__device__ int   g_bsum[256];
// B fragment buffers: [0]=W_gcn, [1]=W1; each 12288 uints (hi 0..6143, lo 6144..12287)
__device__ __align__(16) uint32_t g_bf[2 * 12288];

// ---------------- helpers ----------------
__device__ __forceinline__ uint32_t pack2(float a, float b) {
    __nv_bfloat16 ha = __float2bfloat16_rn(a), hb = __float2bfloat16_rn(b);
    return (uint32_t)__bfloat16_as_ushort(ha) | ((uint32_t)__bfloat16_as_ushort(hb) << 16);
}

__device__ __forceinline__ void split2(float2 f, uint32_t& hi, uint32_t& lo) {
    uint32_t h = pack2(f.x, f.y);
    float hx = __uint_as_float(h << 16);          // low bf16 as f32
    float hy = __uint_as_float(h & 0xFFFF0000u);  // high bf16 as f32
    hi = h;
    lo = pack2(f.x - hx, f.y - hy);
}

// m16n8k8: A reg0 = row g (k pair), reg1 = row g+8; B 1 reg; C 4 regs
__device__ __forceinline__ void mma1688(float* c, uint32_t a0, uint32_t a1, uint32_t b0) {
    asm volatile(
        "mma.sync.aligned.m16n8k8.row.col.f32.bf16.bf16.f32 "
        "{%0,%1,%2,%3}, {%4,%5}, {%6}, {%0,%1,%2,%3};"
        : "+f"(c[0]), "+f"(c[1]), "+f"(c[2]), "+f"(c[3])
        : "r"(a0), "r"(a1), "r"(b0));
}

// pack W[k][n] (HIDN cols) into m16n8k8 fragment order at dst (idx in [0,6144))
__device__ __forceinline__ void pack_one(uint32_t* dst, const float* W, int Ksrc, int idx) {
    int lane = idx & 31, t = idx >> 5;     // t in [0,192)
    int nt = t % 12, kt = t / 12;          // kt in [0,16)
    int g = lane >> 2, tig = lane & 3;
    int n  = nt * 8 + g;
    int k0 = kt * 8 + tig * 2;
    float w0 = (k0     < Ksrc) ? W[(size_t)k0       * HIDN + n] : 0.0f;
    float w1 = (k0 + 1 < Ksrc) ? W[(size_t)(k0 + 1) * HIDN + n] : 0.0f;
    uint32_t hi, lo;
    split2(make_float2(w0, w1), hi, lo);
    dst[idx]        = hi;
    dst[6144 + idx] = lo;
}

// ---------------- init: zero counts + pack BOTH weight matrices (1 launch) ----------
// blocks [0,196): zero g_cnt; [196,220): pack W_gcn -> g_bf[0]; [220,244): W1 -> g_bf[1]
__global__ void __launch_bounds__(256) k_init(const float* __restrict__ W_gcn,
                                              const float* __restrict__ W1, int n) {
    int b = blockIdx.x, tid = threadIdx.x;
    if (b < 196) {
        int i = b * 256 + tid;
        if (i < n) g_cnt[i] = 0;
    } else if (b < 220) {
        pack_one(g_bf, W_gcn, 128, (b - 196) * 256 + tid);
    } else {
        pack_one(g_bf + 12288, W1, HIDN + TEMPF, (b - 220) * 256 + tid);
    }
}

__global__ void k_count(const int* __restrict__ ei, int E) {
    int e = blockIdx.x * blockDim.x + threadIdx.x;
    if (e < E) atomicAdd(&g_cnt[ei[E + e]], 1);
}

// ---------------- scan stage 1 (R13-proven): per-block scan + block totals ----------
__global__ void __launch_bounds__(256) k_scan_blk(int n) {
    __shared__ int ws[8];
    int tid = threadIdx.x, lane = tid & 31, w = tid >> 5;
    int i = blockIdx.x * 256 + tid;
    int v = (i < n) ? g_cnt[i] : 0;
    int x = v;
#pragma unroll
    for (int o = 1; o < 32; o <<= 1) {
        int y = __shfl_up_sync(0xffffffffu, x, o);
        if (lane >= o) x += y;
    }
    if (lane == 31) ws[w] = x;
    __syncthreads();
    if (tid < 8) {
        int y = ws[tid];
#pragma unroll
        for (int o = 1; o < 8; o <<= 1) {
            int z = __shfl_up_sync(0xffu, y, o);
            if ((int)tid >= o) y += z;
        }
        ws[tid] = y;
    }
    __syncthreads();
    int excl = x - v + (w ? ws[w - 1] : 0);
    if (i < n) g_row[i] = excl;
    if (tid == 0) g_bsum[blockIdx.x] = ws[7];
}

// ---------------- scan stage 2 (R13-proven): reduce 196 block sums; add; cursors; dinv
__global__ void __launch_bounds__(256) k_scan_add(int n) {
    __shared__ int ws[8];
    __shared__ int sOff;
    int tid = threadIdx.x, lane = tid & 31, w = tid >> 5;
    int v = (tid < blockIdx.x) ? g_bsum[tid] : 0;
#pragma unroll
    for (int o = 16; o; o >>= 1) v += __shfl_xor_sync(0xffffffffu, v, o);
    if (lane == 0) ws[w] = v;
    __syncthreads();
    if (tid == 0) {
        int s = 0;
#pragma unroll
        for (int q = 0; q < 8; q++) s += ws[q];
        sOff = s;
    }
    __syncthreads();
    int i = blockIdx.x * 256 + tid;
    if (i >= n) return;
    int excl = g_row[i] + sOff;
    g_row [i] = excl;
    g_woff[i] = excl;
    g_dinv[i] = rsqrtf((float)(g_cnt[i] + 1));   // +1 self loop
}

__global__ void k_fill(const int* __restrict__ ei, int E) {
    int e = blockIdx.x * blockDim.x + threadIdx.x;
    if (e >= E) return;
    int src = ei[e];
    int dst = ei[E + e];
    int pos = atomicAdd(&g_woff[dst], 1);
    g_csr[pos] = src;
}

// ---------------- HMMA GEMM: C[128,96] = A[128x128] @ B (2-way bf16 split) ----------
// mode 0: A=A_ext(x), B=g_bf[0];  g_hs[m]=dinv[m]*C[m]; fused g_xw2[m]=x[m].W2[96:224]
// mode 1: A=g_acat,   B=g_bf[1];  out[m] = relu( relu(C[m]+b1).W2[0:96] + xw2[m] + b2 )
// NOTE: device-side selection of A/B (host cannot pass __device__ symbols!)
__global__ void __launch_bounds__(256) k_mma(
    const float* __restrict__ A_ext,
    const float* __restrict__ b1,
    const float* __restrict__ W2,
    const float* __restrict__ b2,
    float* __restrict__ outp,
    int mode, int M)
{
    __shared__ uint32_t sbf[6144];   // 24 KB static: one k-half (hi at 0, lo at 3072)

    const float* __restrict__ A = (mode == 0) ? A_ext : g_acat;
    const uint32_t* __restrict__ bfp = g_bf + mode * 12288;

    int tid  = threadIdx.x;
    int w    = tid >> 5;
    int lane = tid & 31;
    int g    = lane >> 2;
    int tig  = lane & 3;
    int m0   = blockIdx.x * 128 + w * 16 + g;
    int m1   = m0 + 8;
    bool v0  = m0 < M, v1 = m1 < M;

    float acc[12][4];
#pragma unroll
    for (int nt = 0; nt < 12; nt++)
#pragma unroll
        for (int q = 0; q < 4; q++) acc[nt][q] = 0.0f;

    float px0 = 0.0f, px1 = 0.0f;   // mode 0: partial x.W2[96:224]

    const float* a0p = A + (size_t)m0 * GK;
    const float* a1p = A + (size_t)m1 * GK;

    for (int st = 0; st < 2; st++) {
        __syncthreads();   // previous stage reads done before overwrite
        {
            const uint4* srcH = reinterpret_cast<const uint4*>(bfp + st * 3072);
            const uint4* srcL = reinterpret_cast<const uint4*>(bfp + 6144 + st * 3072);
            uint4* dstH = reinterpret_cast<uint4*>(sbf);
            uint4* dstL = reinterpret_cast<uint4*>(sbf + 3072);
#pragma unroll
            for (int i = tid; i < 768; i += 256) { dstH[i] = srcH[i]; dstL[i] = srcL[i]; }
        }
        __syncthreads();

#pragma unroll
        for (int kl = 0; kl < 8; kl++) {
            int c0 = (st * 8 + kl) * 8 + tig * 2;
            float2 z = make_float2(0.f, 0.f);
            float2 fa = v0 ? *reinterpret_cast<const float2*>(a0p + c0) : z;  // row g
            float2 fb = v1 ? *reinterpret_cast<const float2*>(a1p + c0) : z;  // row g+8
            if (mode == 0) {
                float wa = __ldg(W2 + HIDN + c0);
                float wb = __ldg(W2 + HIDN + c0 + 1);
                px0 = fmaf(fa.x, wa, fmaf(fa.y, wb, px0));
                px1 = fmaf(fb.x, wa, fmaf(fb.y, wb, px1));
            }
            uint32_t ah0, al0, ah1, al1;
            split2(fa, ah0, al0);
            split2(fb, ah1, al1);

            int eb = kl * 384 + lane;
#pragma unroll
            for (int nt = 0; nt < 12; nt++) {
                uint32_t bh = sbf[eb + nt * 32];
                uint32_t bl = sbf[3072 + eb + nt * 32];
                mma1688(acc[nt], ah0, ah1, bh);   // ah*bh
                mma1688(acc[nt], ah0, ah1, bl);   // ah*bl
                mma1688(acc[nt], al0, al1, bh);   // al*bh
            }
        }
    }

    if (mode == 0) {
        float s0 = v0 ? g_dinv[m0] : 0.0f;
        float s1 = v1 ? g_dinv[m1] : 0.0f;
#pragma unroll
        for (int nt = 0; nt < 12; nt++) {
            int col = nt * 8 + tig * 2;
            if (v0) *reinterpret_cast<float2*>(g_hs + (size_t)m0 * HIDN + col) =
                        make_float2(acc[nt][0] * s0, acc[nt][1] * s0);
            if (v1) *reinterpret_cast<float2*>(g_hs + (size_t)m1 * HIDN + col) =
                        make_float2(acc[nt][2] * s1, acc[nt][3] * s1);
        }
        px0 += __shfl_xor_sync(0xffffffffu, px0, 1);
        px0 += __shfl_xor_sync(0xffffffffu, px0, 2);
        px1 += __shfl_xor_sync(0xffffffffu, px1, 1);
        px1 += __shfl_xor_sync(0xffffffffu, px1, 2);
        if (tig == 0) {
            if (v0) g_xw2[m0] = px0;
            if (v1) g_xw2[m1] = px1;
        }
    } else {
        float p0 = 0.0f, p1 = 0.0f;
#pragma unroll
        for (int nt = 0; nt < 12; nt++) {
            int col = nt * 8 + tig * 2;
            float bb0 = __ldg(b1 + col), bb1 = __ldg(b1 + col + 1);
            float ww0 = __ldg(W2 + col), ww1 = __ldg(W2 + col + 1);
            p0 = fmaf(fmaxf(acc[nt][0] + bb0, 0.0f), ww0, p0);
            p0 = fmaf(fmaxf(acc[nt][1] + bb1, 0.0f), ww1, p0);
            p1 = fmaf(fmaxf(acc[nt][2] + bb0, 0.0f), ww0, p1);
            p1 = fmaf(fmaxf(acc[nt][3] + bb1, 0.0f), ww1, p1);
        }
        p0 += __shfl_xor_sync(0xffffffffu, p0, 1);
        p0 += __shfl_xor_sync(0xffffffffu, p0, 2);
        p1 += __shfl_xor_sync(0xffffffffu, p1, 1);
        p1 += __shfl_xor_sync(0xffffffffu, p1, 2);
        if (tig == 0) {
            float b2v = __ldg(b2);
            if (v0) outp[m0] = fmaxf(p0 + g_xw2[m0] + b2v, 0.0f);
            if (v1) outp[m1] = fmaxf(p1 + g_xw2[m1] + b2v, 0.0f);
        }
    }
}

// ---------------- gather segment-sum + fused acat pack (proven) ----------------
__global__ void __launch_bounds__(256) k_gather(
    const float* __restrict__ temporal,
    const float* __restrict__ b_gcn, int n)
{
    int gw   = (blockIdx.x * blockDim.x + threadIdx.x) >> 5;
    int lane = threadIdx.x & 31;
    if (gw >= n) return;
    int i = gw;

    float4 acc = make_float4(0.f, 0.f, 0.f, 0.f);
    if (lane < 24)
        acc = reinterpret_cast<const float4*>(g_hs)[(size_t)i * 24 + lane];  // self loop

    int start = g_row[i];
    int cnt   = g_cnt[i];
    for (int base = 0; base < cnt; base += 32) {
        int e = base + lane;
        int s = (e < cnt) ? g_csr[start + e] : 0;
        int m = min(32, cnt - base);
        int j = 0;
        for (; j + 2 <= m; j += 2) {
            int s0 = __shfl_sync(0xffffffffu, s, j);
            int s1 = __shfl_sync(0xffffffffu, s, j + 1);
            if (lane < 24) {
                float4 v0 = reinterpret_cast<const float4*>(g_hs)[(size_t)s0 * 24 + lane];
                float4 v1 = reinterpret_cast<const float4*>(g_hs)[(size_t)s1 * 24 + lane];
                acc.x += v0.x + v1.x; acc.y += v0.y + v1.y;
                acc.z += v0.z + v1.z; acc.w += v0.w + v1.w;
            }
        }
        if (j < m) {
            int s0 = __shfl_sync(0xffffffffu, s, j);
            if (lane < 24) {
                float4 v0 = reinterpret_cast<const float4*>(g_hs)[(size_t)s0 * 24 + lane];
                acc.x += v0.x; acc.y += v0.y; acc.z += v0.z; acc.w += v0.w;
            }
        }
    }

    float di = g_dinv[i];
    if (lane < 24) {
        float4 b = reinterpret_cast<const float4*>(b_gcn)[lane];
        float4 o;
        o.x = fmaxf(fmaf(di, acc.x, b.x), 0.0f);
        o.y = fmaxf(fmaf(di, acc.y, b.y), 0.0f);
        o.z = fmaxf(fmaf(di, acc.z, b.z), 0.0f);
        o.w = fmaxf(fmaf(di, acc.w, b.w), 0.0f);
        reinterpret_cast<float4*>(g_acat)[(size_t)i * 32 + lane] = o;
    } else {
#pragma unroll
        for (int q = 0; q < 4; q++) {
            int c = 96 + (lane - 24) * 4 + q;
            float v = (c < HIDN + TEMPF) ? temporal[(size_t)i * TEMPF + (c - HIDN)] : 0.0f;
            g_acat[(size_t)i * GK + c] = v;
        }
    }
}

// ---------------- launch ----------------
extern "C" void kernel_launch(void* const* d_in, const int* in_sizes, int n_in,
                              void* d_out, int out_size) {
    const float* x        = (const float*)d_in[0];
    const int*   ei       = (const int*)  d_in[1];   // int32 (JAX x64 disabled)
    const float* temporal = (const float*)d_in[2];
    const float* W_gcn    = (const float*)d_in[3];
    const float* b_gcn    = (const float*)d_in[4];
    const float* W1       = (const float*)d_in[5];
    const float* b1       = (const float*)d_in[6];
    const float* W2       = (const float*)d_in[7];
    const float* b2       = (const float*)d_in[8];
    float*       out      = (float*)d_out;

    int N  = in_sizes[0] / NODEF;   // 50000
    int E  = in_sizes[1] / 2;       // 800000
    int nb = (N + 255) / 256;       // 196
    int ng = (N + 127) / 128;       // 391 HMMA tiles

    k_init     <<<nb + 48, 256>>>(W_gcn, W1, N);     // zero cnt + pack both B
    k_count    <<<(E + 255) / 256, 256>>>(ei, E);
    k_scan_blk <<<nb, 256>>>(N);
    k_scan_add <<<nb, 256>>>(N);
    k_fill     <<<(E + 255) / 256, 256>>>(ei, E);

    // GEMM1: g_hs = dinv * (x @ W_gcn); fused g_xw2 = x . W2[96:224]
    k_mma      <<<ng, 256>>>(x, nullptr, W2, nullptr, nullptr, 0, N);

    k_gather   <<<(N * 32 + 255) / 256, 256>>>(temporal, b_gcn, N);   // g_acat

    // GEMM2 + fused final: out = relu(relu(acat@W1+b1).W2[0:96] + xw2 + b2)
    k_mma      <<<ng, 256>>>(nullptr, b1, W2, b2, out, 1, N);
}

// round 16
// speedup vs baseline: 1.1734x; 1.1205x over previous
#include <cuda_runtime.h>
#include <cuda_bf16.h>
#include <cstdint>

// ---------------- problem constants ----------------
#define NN     50000
#define EE     800000
#define HIDN   96
#define GK     128      // fp32 A row stride (x and acat both 128 wide)
#define NODEF  128
#define TEMPF  10

// ---------------- device scratch ----------------
__device__ __align__(16) float g_dinv [NN];
__device__ __align__(16) float g_hs   [NN * HIDN];
__device__ __align__(16) float g_acat [NN * GK];
__device__ __align__(16) float g_xw2  [NN];
__device__ int   g_cnt [NN];
__device__ int   g_row [NN];
__device__ int   g_woff[NN];
__device__ int   g_csr [EE];
__device__ int   g_bsum[256];
// B in m16n8k16 fragment order: uint2 per (kt,nt,lane); [0..3071]=hi, [3072..6143]=lo
__device__ __align__(16) uint2 g_bf[6144];

// ---------------- helpers ----------------
__device__ __forceinline__ uint32_t pack2(float a, float b) {
    __nv_bfloat16 ha = __float2bfloat16_rn(a), hb = __float2bfloat16_rn(b);
    return (uint32_t)__bfloat16_as_ushort(ha) | ((uint32_t)__bfloat16_as_ushort(hb) << 16);
}

__device__ __forceinline__ void split2(float2 f, uint32_t& hi, uint32_t& lo) {
    uint32_t h = pack2(f.x, f.y);
    float hx = __uint_as_float(h << 16);          // low bf16 as f32
    float hy = __uint_as_float(h & 0xFFFF0000u);  // high bf16 as f32
    hi = h;
    lo = pack2(f.x - hx, f.y - hy);
}

// m16n8k16: a0=(row g, k 2t..2t+1) a1=(g+8, 2t..) a2=(g, 2t+8..) a3=(g+8, 2t+8..)
//           b0=(n g, k 2t..2t+1)   b1=(n g, k 2t+8..2t+9)
__device__ __forceinline__ void mma16816(float* c, const uint32_t* a,
                                         uint32_t b0, uint32_t b1) {
    asm volatile(
        "mma.sync.aligned.m16n8k16.row.col.f32.bf16.bf16.f32 "
        "{%0,%1,%2,%3}, {%4,%5,%6,%7}, {%8,%9}, {%0,%1,%2,%3};"
        : "+f"(c[0]), "+f"(c[1]), "+f"(c[2]), "+f"(c[3])
        : "r"(a[0]), "r"(a[1]), "r"(a[2]), "r"(a[3]), "r"(b0), "r"(b1));
}

// ---------------- CSR build (R13-proven) ----------------
__global__ void k_zero_cnt(int n) {
    int i = blockIdx.x * blockDim.x + threadIdx.x;
    if (i < n) g_cnt[i] = 0;
}

__global__ void k_count(const int* __restrict__ ei, int E) {
    int e = blockIdx.x * blockDim.x + threadIdx.x;
    if (e < E) atomicAdd(&g_cnt[ei[E + e]], 1);
}

__global__ void __launch_bounds__(256) k_scan_blk(int n) {
    __shared__ int ws[8];
    int tid = threadIdx.x, lane = tid & 31, w = tid >> 5;
    int i = blockIdx.x * 256 + tid;
    int v = (i < n) ? g_cnt[i] : 0;
    int x = v;
#pragma unroll
    for (int o = 1; o < 32; o <<= 1) {
        int y = __shfl_up_sync(0xffffffffu, x, o);
        if (lane >= o) x += y;
    }
    if (lane == 31) ws[w] = x;
    __syncthreads();
    if (tid < 8) {
        int y = ws[tid];
#pragma unroll
        for (int o = 1; o < 8; o <<= 1) {
            int z = __shfl_up_sync(0xffu, y, o);
            if ((int)tid >= o) y += z;
        }
        ws[tid] = y;
    }
    __syncthreads();
    int excl = x - v + (w ? ws[w - 1] : 0);
    if (i < n) g_row[i] = excl;
    if (tid == 0) g_bsum[blockIdx.x] = ws[7];
}

__global__ void __launch_bounds__(256) k_scan_add(int n) {
    __shared__ int ws[8];
    __shared__ int sOff;
    int tid = threadIdx.x, lane = tid & 31, w = tid >> 5;
    int v = (tid < blockIdx.x) ? g_bsum[tid] : 0;
#pragma unroll
    for (int o = 16; o; o >>= 1) v += __shfl_xor_sync(0xffffffffu, v, o);
    if (lane == 0) ws[w] = v;
    __syncthreads();
    if (tid == 0) {
        int s = 0;
#pragma unroll
        for (int q = 0; q < 8; q++) s += ws[q];
        sOff = s;
    }
    __syncthreads();
    int i = blockIdx.x * 256 + tid;
    if (i >= n) return;
    int excl = g_row[i] + sOff;
    g_row [i] = excl;
    g_woff[i] = excl;
    g_dinv[i] = rsqrtf((float)(g_cnt[i] + 1));   // +1 self loop
}

__global__ void k_fill(const int* __restrict__ ei, int E) {
    int e = blockIdx.x * blockDim.x + threadIdx.x;
    if (e >= E) return;
    int src = ei[e];
    int dst = ei[E + e];
    int pos = atomicAdd(&g_woff[dst], 1);
    g_csr[pos] = src;
}

// ---------------- pack B [Ksrc x 96] into m16n8k16 fragment order (bf16 hi/lo) ------
__global__ void k_packbf(const float* __restrict__ W, int Ksrc) {
    int idx = blockIdx.x * blockDim.x + threadIdx.x;   // [0,3072)
    if (idx >= 3072) return;
    int lane = idx & 31, t = idx >> 5;     // t in [0,96)
    int nt = t % 12, kt = t / 12;          // kt in [0,8)
    int g = lane >> 2, tig = lane & 3;
    int n  = nt * 8 + g;
    int k0 = kt * 16 + tig * 2;
    float w00 = (k0     < Ksrc) ? W[(size_t)k0       * HIDN + n] : 0.0f;
    float w01 = (k0 + 1 < Ksrc) ? W[(size_t)(k0 + 1) * HIDN + n] : 0.0f;
    float w10 = (k0 + 8 < Ksrc) ? W[(size_t)(k0 + 8) * HIDN + n] : 0.0f;
    float w11 = (k0 + 9 < Ksrc) ? W[(size_t)(k0 + 9) * HIDN + n] : 0.0f;
    uint32_t h0, l0, h1, l1;
    split2(make_float2(w00, w01), h0, l0);
    split2(make_float2(w10, w11), h1, l1);
    g_bf[idx]        = make_uint2(h0, h1);   // hi: (b0,b1)
    g_bf[3072 + idx] = make_uint2(l0, l1);   // lo
}

// ---------------- HMMA GEMM: C[128,96] = A[128x128] @ B (2-way bf16 split, k16) -----
// mode 0: A=A_ext(x);  g_hs[m]=dinv[m]*C[m]; fused g_xw2[m]=x[m].W2[96:224]
// mode 1: A=g_acat;    out[m] = relu( relu(C[m]+b1).W2[0:96] + xw2[m] + b2 )
// NOTE: device-side selection of A (host cannot pass __device__ symbols!)
__global__ void __launch_bounds__(256) k_mma(
    const float* __restrict__ A_ext,
    const float* __restrict__ b1,
    const float* __restrict__ W2,
    const float* __restrict__ b2,
    float* __restrict__ outp,
    int mode, int M)
{
    __shared__ uint2 sbf[3072];   // 24 KB static: one k-half (hi [0,1536), lo [1536,3072))

    const float* __restrict__ A = (mode == 0) ? A_ext : g_acat;

    int tid  = threadIdx.x;
    int w    = tid >> 5;
    int lane = tid & 31;
    int g    = lane >> 2;
    int tig  = lane & 3;
    int m0   = blockIdx.x * 128 + w * 16 + g;
    int m1   = m0 + 8;
    bool v0  = m0 < M, v1 = m1 < M;

    float acc[12][4];
#pragma unroll
    for (int nt = 0; nt < 12; nt++)
#pragma unroll
        for (int q = 0; q < 4; q++) acc[nt][q] = 0.0f;

    float px0 = 0.0f, px1 = 0.0f;   // mode 0: partial x.W2[96:224]

    const float* a0p = A + (size_t)m0 * GK;
    const float* a1p = A + (size_t)m1 * GK;

    for (int st = 0; st < 2; st++) {
        __syncthreads();   // previous stage reads done before overwrite
        {
            const uint4* srcH = reinterpret_cast<const uint4*>(g_bf + st * 1536);
            const uint4* srcL = reinterpret_cast<const uint4*>(g_bf + 3072 + st * 1536);
            uint4* dstH = reinterpret_cast<uint4*>(sbf);
            uint4* dstL = reinterpret_cast<uint4*>(sbf + 1536);
#pragma unroll
            for (int i = tid; i < 768; i += 256) { dstH[i] = srcH[i]; dstL[i] = srcL[i]; }
        }
        __syncthreads();

#pragma unroll
        for (int kl = 0; kl < 4; kl++) {
            int c0 = (st * 4 + kl) * 16 + tig * 2;
            float2 z = make_float2(0.f, 0.f);
            float2 fa = v0 ? *reinterpret_cast<const float2*>(a0p + c0)     : z; // g,   k
            float2 fb = v1 ? *reinterpret_cast<const float2*>(a1p + c0)     : z; // g+8, k
            float2 fc = v0 ? *reinterpret_cast<const float2*>(a0p + c0 + 8) : z; // g,   k+8
            float2 fd = v1 ? *reinterpret_cast<const float2*>(a1p + c0 + 8) : z; // g+8, k+8
            if (mode == 0) {
                float wa0 = __ldg(W2 + HIDN + c0),     wa1 = __ldg(W2 + HIDN + c0 + 1);
                float wc0 = __ldg(W2 + HIDN + c0 + 8), wc1 = __ldg(W2 + HIDN + c0 + 9);
                px0 = fmaf(fa.x, wa0, fmaf(fa.y, wa1, fmaf(fc.x, wc0, fmaf(fc.y, wc1, px0))));
                px1 = fmaf(fb.x, wa0, fmaf(fb.y, wa1, fmaf(fd.x, wc0, fmaf(fd.y, wc1, px1))));
            }
            uint32_t ah[4], al[4];
            split2(fa, ah[0], al[0]);
            split2(fb, ah[1], al[1]);
            split2(fc, ah[2], al[2]);
            split2(fd, ah[3], al[3]);

            int eb = kl * 384 + lane;
#pragma unroll
            for (int nt = 0; nt < 12; nt++) {
                uint2 bh = sbf[eb + nt * 32];
                uint2 bl = sbf[1536 + eb + nt * 32];
                mma16816(acc[nt], ah, bh.x, bh.y);   // ah*bh
                mma16816(acc[nt], ah, bl.x, bl.y);   // ah*bl
                mma16816(acc[nt], al, bh.x, bh.y);   // al*bh
            }
        }
    }

    if (mode == 0) {
        float s0 = v0 ? g_dinv[m0] : 0.0f;
        float s1 = v1 ? g_dinv[m1] : 0.0f;
#pragma unroll
        for (int nt = 0; nt < 12; nt++) {
            int col = nt * 8 + tig * 2;
            if (v0) *reinterpret_cast<float2*>(g_hs + (size_t)m0 * HIDN + col) =
                        make_float2(acc[nt][0] * s0, acc[nt][1] * s0);
            if (v1) *reinterpret_cast<float2*>(g_hs + (size_t)m1 * HIDN + col) =
                        make_float2(acc[nt][2] * s1, acc[nt][3] * s1);
        }
        px0 += __shfl_xor_sync(0xffffffffu, px0, 1);
        px0 += __shfl_xor_sync(0xffffffffu, px0, 2);
        px1 += __shfl_xor_sync(0xffffffffu, px1, 1);
        px1 += __shfl_xor_sync(0xffffffffu, px1, 2);
        if (tig == 0) {
            if (v0) g_xw2[m0] = px0;
            if (v1) g_xw2[m1] = px1;
        }
    } else {
        float p0 = 0.0f, p1 = 0.0f;
#pragma unroll
        for (int nt = 0; nt < 12; nt++) {
            int col = nt * 8 + tig * 2;
            float bb0 = __ldg(b1 + col), bb1 = __ldg(b1 + col + 1);
            float ww0 = __ldg(W2 + col), ww1 = __ldg(W2 + col + 1);
            p0 = fmaf(fmaxf(acc[nt][0] + bb0, 0.0f), ww0, p0);
            p0 = fmaf(fmaxf(acc[nt][1] + bb1, 0.0f), ww1, p0);
            p1 = fmaf(fmaxf(acc[nt][2] + bb0, 0.0f), ww0, p1);
            p1 = fmaf(fmaxf(acc[nt][3] + bb1, 0.0f), ww1, p1);
        }
        p0 += __shfl_xor_sync(0xffffffffu, p0, 1);
        p0 += __shfl_xor_sync(0xffffffffu, p0, 2);
        p1 += __shfl_xor_sync(0xffffffffu, p1, 1);
        p1 += __shfl_xor_sync(0xffffffffu, p1, 2);
        if (tig == 0) {
            float b2v = __ldg(b2);
            if (v0) outp[m0] = fmaxf(p0 + g_xw2[m0] + b2v, 0.0f);
            if (v1) outp[m1] = fmaxf(p1 + g_xw2[m1] + b2v, 0.0f);
        }
    }
}

// ---------------- gather segment-sum + fused acat pack (proven) ----------------
__global__ void __launch_bounds__(256) k_gather(
    const float* __restrict__ temporal,
    const float* __restrict__ b_gcn, int n)
{
    int gw   = (blockIdx.x * blockDim.x + threadIdx.x) >> 5;
    int lane = threadIdx.x & 31;
    if (gw >= n) return;
    int i = gw;

    float4 acc = make_float4(0.f, 0.f, 0.f, 0.f);
    if (lane < 24)
        acc = reinterpret_cast<const float4*>(g_hs)[(size_t)i * 24 + lane];  // self loop

    int start = g_row[i];
    int cnt   = g_cnt[i];
    for (int base = 0; base < cnt; base += 32) {
        int e = base + lane;
        int s = (e < cnt) ? g_csr[start + e] : 0;
        int m = min(32, cnt - base);
        int j = 0;
        for (; j + 2 <= m; j += 2) {
            int s0 = __shfl_sync(0xffffffffu, s, j);
            int s1 = __shfl_sync(0xffffffffu, s, j + 1);
            if (lane < 24) {
                float4 v0 = reinterpret_cast<const float4*>(g_hs)[(size_t)s0 * 24 + lane];
                float4 v1 = reinterpret_cast<const float4*>(g_hs)[(size_t)s1 * 24 + lane];
                acc.x += v0.x + v1.x; acc.y += v0.y + v1.y;
                acc.z += v0.z + v1.z; acc.w += v0.w + v1.w;
            }
        }
        if (j < m) {
            int s0 = __shfl_sync(0xffffffffu, s, j);
            if (lane < 24) {
                float4 v0 = reinterpret_cast<const float4*>(g_hs)[(size_t)s0 * 24 + lane];
                acc.x += v0.x; acc.y += v0.y; acc.z += v0.z; acc.w += v0.w;
            }
        }
    }

    float di = g_dinv[i];
    if (lane < 24) {
        float4 b = reinterpret_cast<const float4*>(b_gcn)[lane];
        float4 o;
        o.x = fmaxf(fmaf(di, acc.x, b.x), 0.0f);
        o.y = fmaxf(fmaf(di, acc.y, b.y), 0.0f);
        o.z = fmaxf(fmaf(di, acc.z, b.z), 0.0f);
        o.w = fmaxf(fmaf(di, acc.w, b.w), 0.0f);
        reinterpret_cast<float4*>(g_acat)[(size_t)i * 32 + lane] = o;
    } else {
#pragma unroll
        for (int q = 0; q < 4; q++) {
            int c = 96 + (lane - 24) * 4 + q;
            float v = (c < HIDN + TEMPF) ? temporal[(size_t)i * TEMPF + (c - HIDN)] : 0.0f;
            g_acat[(size_t)i * GK + c] = v;
        }
    }
}

// ---------------- launch (R13-identical schedule) ----------------
extern "C" void kernel_launch(void* const* d_in, const int* in_sizes, int n_in,
                              void* d_out, int out_size) {
    const float* x        = (const float*)d_in[0];
    const int*   ei       = (const int*)  d_in[1];   // int32 (JAX x64 disabled)
    const float* temporal = (const float*)d_in[2];
    const float* W_gcn    = (const float*)d_in[3];
    const float* b_gcn    = (const float*)d_in[4];
    const float* W1       = (const float*)d_in[5];
    const float* b1       = (const float*)d_in[6];
    const float* W2       = (const float*)d_in[7];
    const float* b2       = (const float*)d_in[8];
    float*       out      = (float*)d_out;

    int N  = in_sizes[0] / NODEF;   // 50000
    int E  = in_sizes[1] / 2;       // 800000
    int nb = (N + 255) / 256;       // 196
    int ng = (N + 127) / 128;       // 391 HMMA tiles
    const int KS2 = HIDN + TEMPF;   // 106

    k_zero_cnt <<<nb, 256>>>(N);
    k_count    <<<(E + 255) / 256, 256>>>(ei, E);
    k_scan_blk <<<nb, 256>>>(N);
    k_scan_add <<<nb, 256>>>(N);
    k_fill     <<<(E + 255) / 256, 256>>>(ei, E);

    // GEMM1: g_hs = dinv * (x @ W_gcn); fused g_xw2 = x . W2[96:224]
    k_packbf   <<<12, 256>>>(W_gcn, 128);
    k_mma      <<<ng, 256>>>(x, nullptr, W2, nullptr, nullptr, 0, N);

    k_gather   <<<(N * 32 + 255) / 256, 256>>>(temporal, b_gcn, N);   // g_acat

    // GEMM2 + fused final: out = relu(relu(acat@W1+b1).W2[0:96] + xw2 + b2)
    k_packbf   <<<12, 256>>>(W1, KS2);
    k_mma      <<<ng, 256>>>(nullptr, b1, W2, b2, out, 1, N);
}

// round 17
// speedup vs baseline: 1.2205x; 1.0402x over previous
#include <cuda_runtime.h>
#include <cuda_bf16.h>
#include <cstdint>

// ---------------- problem constants ----------------
#define NN     50000
#define EE     800000
#define HIDN   96
#define GK     128      // fp32 A row stride (x and acat both 128 wide)
#define NODEF  128
#define TEMPF  10

// ---------------- device scratch ----------------
__device__ __align__(16) float g_dinv [NN];
__device__ __align__(16) float g_xw   [NN * HIDN];   // RAW x @ W_gcn (dinv applied in gather)
__device__ __align__(16) float g_acat [NN * GK];
__device__ __align__(16) float g_xw2  [NN];
__device__ int   g_cnt [NN];
__device__ int   g_row [NN];
__device__ int   g_woff[NN];
__device__ int   g_csr [EE];
__device__ int   g_bsum[256];
// B fragment buffers (m16n8k16): slot0=W_gcn, slot1=W1; each 6144 uint2 (hi 0..3071, lo 3072..6143)
__device__ __align__(16) uint2 g_bf[2 * 6144];

// ---------------- helpers ----------------
__device__ __forceinline__ uint32_t pack2(float a, float b) {
    __nv_bfloat16 ha = __float2bfloat16_rn(a), hb = __float2bfloat16_rn(b);
    return (uint32_t)__bfloat16_as_ushort(ha) | ((uint32_t)__bfloat16_as_ushort(hb) << 16);
}

__device__ __forceinline__ void split2(float2 f, uint32_t& hi, uint32_t& lo) {
    uint32_t h = pack2(f.x, f.y);
    float hx = __uint_as_float(h << 16);          // low bf16 as f32
    float hy = __uint_as_float(h & 0xFFFF0000u);  // high bf16 as f32
    hi = h;
    lo = pack2(f.x - hx, f.y - hy);
}

// m16n8k16: a0=(row g, k 2t..) a1=(g+8, 2t..) a2=(g, 2t+8..) a3=(g+8, 2t+8..); b0/b1 = k/k+8
__device__ __forceinline__ void mma16816(float* c, const uint32_t* a,
                                         uint32_t b0, uint32_t b1) {
    asm volatile(
        "mma.sync.aligned.m16n8k16.row.col.f32.bf16.bf16.f32 "
        "{%0,%1,%2,%3}, {%4,%5,%6,%7}, {%8,%9}, {%0,%1,%2,%3};"
        : "+f"(c[0]), "+f"(c[1]), "+f"(c[2]), "+f"(c[3])
        : "r"(a[0]), "r"(a[1]), "r"(a[2]), "r"(a[3]), "r"(b0), "r"(b1));
}

// ---------------- CSR helpers (R16-proven) ----------------
__global__ void k_zero_cnt(int n) {
    int i = blockIdx.x * blockDim.x + threadIdx.x;
    if (i < n) g_cnt[i] = 0;
}

__global__ void __launch_bounds__(256) k_scan_blk(int n) {
    __shared__ int ws[8];
    int tid = threadIdx.x, lane = tid & 31, w = tid >> 5;
    int i = blockIdx.x * 256 + tid;
    int v = (i < n) ? g_cnt[i] : 0;
    int x = v;
#pragma unroll
    for (int o = 1; o < 32; o <<= 1) {
        int y = __shfl_up_sync(0xffffffffu, x, o);
        if (lane >= o) x += y;
    }
    if (lane == 31) ws[w] = x;
    __syncthreads();
    if (tid < 8) {
        int y = ws[tid];
#pragma unroll
        for (int o = 1; o < 8; o <<= 1) {
            int z = __shfl_up_sync(0xffu, y, o);
            if ((int)tid >= o) y += z;
        }
        ws[tid] = y;
    }
    __syncthreads();
    int excl = x - v + (w ? ws[w - 1] : 0);
    if (i < n) g_row[i] = excl;
    if (tid == 0) g_bsum[blockIdx.x] = ws[7];
}

__global__ void __launch_bounds__(256) k_scan_add(int n) {
    __shared__ int ws[8];
    __shared__ int sOff;
    int tid = threadIdx.x, lane = tid & 31, w = tid >> 5;
    int v = (tid < blockIdx.x) ? g_bsum[tid] : 0;
#pragma unroll
    for (int o = 16; o; o >>= 1) v += __shfl_xor_sync(0xffffffffu, v, o);
    if (lane == 0) ws[w] = v;
    __syncthreads();
    if (tid == 0) {
        int s = 0;
#pragma unroll
        for (int q = 0; q < 8; q++) s += ws[q];
        sOff = s;
    }
    __syncthreads();
    int i = blockIdx.x * 256 + tid;
    if (i >= n) return;
    int excl = g_row[i] + sOff;
    g_row [i] = excl;
    g_woff[i] = excl;
    g_dinv[i] = rsqrtf((float)(g_cnt[i] + 1));   // +1 self loop
}

__global__ void k_fill(const int* __restrict__ ei, int E) {
    int e = blockIdx.x * blockDim.x + threadIdx.x;
    if (e >= E) return;
    int src = ei[e];
    int dst = ei[E + e];
    int pos = atomicAdd(&g_woff[dst], 1);
    g_csr[pos] = src;
}

// ---------------- pack B [Ksrc x 96] into m16n8k16 fragment order (bf16 hi/lo) ------
__global__ void k_packbf(const float* __restrict__ W, int Ksrc, int slot) {
    int idx = blockIdx.x * blockDim.x + threadIdx.x;   // [0,3072)
    if (idx >= 3072) return;
    int lane = idx & 31, t = idx >> 5;     // t in [0,96)
    int nt = t % 12, kt = t / 12;          // kt in [0,8)
    int g = lane >> 2, tig = lane & 3;
    int n  = nt * 8 + g;
    int k0 = kt * 16 + tig * 2;
    float w00 = (k0     < Ksrc) ? W[(size_t)k0       * HIDN + n] : 0.0f;
    float w01 = (k0 + 1 < Ksrc) ? W[(size_t)(k0 + 1) * HIDN + n] : 0.0f;
    float w10 = (k0 + 8 < Ksrc) ? W[(size_t)(k0 + 8) * HIDN + n] : 0.0f;
    float w11 = (k0 + 9 < Ksrc) ? W[(size_t)(k0 + 9) * HIDN + n] : 0.0f;
    uint32_t h0, l0, h1, l1;
    split2(make_float2(w00, w01), h0, l0);
    split2(make_float2(w10, w11), h1, l1);
    uint2* dst = g_bf + slot * 6144;
    dst[idx]        = make_uint2(h0, h1);   // hi: (b0,b1)
    dst[3072 + idx] = make_uint2(l0, l1);   // lo
}

// ---------------- shared GEMM mainloop macro body via device fn ----------------
// computes acc[12][4] = A_tile @ B(slot) for rows m0/m1; optional xw2 partials
struct MmaOut { float px0, px1; };
template<bool XW2>
__device__ __forceinline__ MmaOut gemm_core(
    uint2* sbf, const uint2* bfp,
    const float* __restrict__ a0p, const float* __restrict__ a1p,
    bool v0, bool v1, int tig, int tid,
    const float* __restrict__ W2, float acc[12][4])
{
    MmaOut o; o.px0 = 0.0f; o.px1 = 0.0f;
    for (int st = 0; st < 2; st++) {
        __syncthreads();
        {
            const uint4* srcH = reinterpret_cast<const uint4*>(bfp + st * 1536);
            const uint4* srcL = reinterpret_cast<const uint4*>(bfp + 3072 + st * 1536);
            uint4* dstH = reinterpret_cast<uint4*>(sbf);
            uint4* dstL = reinterpret_cast<uint4*>(sbf + 1536);
#pragma unroll
            for (int i = tid; i < 768; i += 256) { dstH[i] = srcH[i]; dstL[i] = srcL[i]; }
        }
        __syncthreads();

#pragma unroll
        for (int kl = 0; kl < 4; kl++) {
            int c0 = (st * 4 + kl) * 16 + tig * 2;
            float2 z = make_float2(0.f, 0.f);
            float2 fa = v0 ? *reinterpret_cast<const float2*>(a0p + c0)     : z;
            float2 fb = v1 ? *reinterpret_cast<const float2*>(a1p + c0)     : z;
            float2 fc = v0 ? *reinterpret_cast<const float2*>(a0p + c0 + 8) : z;
            float2 fd = v1 ? *reinterpret_cast<const float2*>(a1p + c0 + 8) : z;
            if (XW2) {
                float wa0 = __ldg(W2 + HIDN + c0),     wa1 = __ldg(W2 + HIDN + c0 + 1);
                float wc0 = __ldg(W2 + HIDN + c0 + 8), wc1 = __ldg(W2 + HIDN + c0 + 9);
                o.px0 = fmaf(fa.x, wa0, fmaf(fa.y, wa1, fmaf(fc.x, wc0, fmaf(fc.y, wc1, o.px0))));
                o.px1 = fmaf(fb.x, wa0, fmaf(fb.y, wa1, fmaf(fd.x, wc0, fmaf(fd.y, wc1, o.px1))));
            }
            uint32_t ah[4], al[4];
            split2(fa, ah[0], al[0]);
            split2(fb, ah[1], al[1]);
            split2(fc, ah[2], al[2]);
            split2(fd, ah[3], al[3]);

            int eb = kl * 384 + (tid & 31);
#pragma unroll
            for (int nt = 0; nt < 12; nt++) {
                uint2 bh = sbf[eb + nt * 32];
                uint2 bl = sbf[1536 + eb + nt * 32];
                mma16816(acc[nt], ah, bh.x, bh.y);
                mma16816(acc[nt], ah, bl.x, bl.y);
                mma16816(acc[nt], al, bh.x, bh.y);
            }
        }
    }
    return o;
}

// ---------------- k_front: GEMM1 (raw, + xw2) blocks [0,ng) ∥ count blocks [ng,..) ----
__global__ void __launch_bounds__(256) k_front(
    const int* __restrict__ ei, int E,
    const float* __restrict__ x,
    const float* __restrict__ W2,
    int M, int ng)
{
    __shared__ uint2 sbf[3072];

    if ((int)blockIdx.x >= ng) {
        int e = ((int)blockIdx.x - ng) * 256 + threadIdx.x;
        if (e < E) atomicAdd(&g_cnt[ei[E + e]], 1);
        return;
    }

    int tid  = threadIdx.x;
    int w    = tid >> 5;
    int lane = tid & 31;
    int g    = lane >> 2;
    int tig  = lane & 3;
    int m0   = blockIdx.x * 128 + w * 16 + g;
    int m1   = m0 + 8;
    bool v0  = m0 < M, v1 = m1 < M;

    float acc[12][4];
#pragma unroll
    for (int nt = 0; nt < 12; nt++)
#pragma unroll
        for (int q = 0; q < 4; q++) acc[nt][q] = 0.0f;

    MmaOut r = gemm_core<true>(sbf, g_bf, x + (size_t)m0 * GK, x + (size_t)m1 * GK,
                               v0, v1, tig, tid, W2, acc);

    // epilogue: RAW store (dinv deferred to gather)
#pragma unroll
    for (int nt = 0; nt < 12; nt++) {
        int col = nt * 8 + tig * 2;
        if (v0) *reinterpret_cast<float2*>(g_xw + (size_t)m0 * HIDN + col) =
                    make_float2(acc[nt][0], acc[nt][1]);
        if (v1) *reinterpret_cast<float2*>(g_xw + (size_t)m1 * HIDN + col) =
                    make_float2(acc[nt][2], acc[nt][3]);
    }
    float px0 = r.px0, px1 = r.px1;
    px0 += __shfl_xor_sync(0xffffffffu, px0, 1);
    px0 += __shfl_xor_sync(0xffffffffu, px0, 2);
    px1 += __shfl_xor_sync(0xffffffffu, px1, 1);
    px1 += __shfl_xor_sync(0xffffffffu, px1, 2);
    if (tig == 0) {
        if (v0) g_xw2[m0] = px0;
        if (v1) g_xw2[m1] = px1;
    }
}

// ---------------- k_mma1: GEMM2 + fused final ----------------
__global__ void __launch_bounds__(256) k_mma1(
    const float* __restrict__ b1,
    const float* __restrict__ W2,
    const float* __restrict__ b2,
    float* __restrict__ outp, int M)
{
    __shared__ uint2 sbf[3072];

    int tid  = threadIdx.x;
    int w    = tid >> 5;
    int lane = tid & 31;
    int g    = lane >> 2;
    int tig  = lane & 3;
    int m0   = blockIdx.x * 128 + w * 16 + g;
    int m1   = m0 + 8;
    bool v0  = m0 < M, v1 = m1 < M;

    float acc[12][4];
#pragma unroll
    for (int nt = 0; nt < 12; nt++)
#pragma unroll
        for (int q = 0; q < 4; q++) acc[nt][q] = 0.0f;

    gemm_core<false>(sbf, g_bf + 6144,
                     g_acat + (size_t)m0 * GK, g_acat + (size_t)m1 * GK,
                     v0, v1, tig, tid, nullptr, acc);

    float p0 = 0.0f, p1 = 0.0f;
#pragma unroll
    for (int nt = 0; nt < 12; nt++) {
        int col = nt * 8 + tig * 2;
        float bb0 = __ldg(b1 + col), bb1 = __ldg(b1 + col + 1);
        float ww0 = __ldg(W2 + col), ww1 = __ldg(W2 + col + 1);
        p0 = fmaf(fmaxf(acc[nt][0] + bb0, 0.0f), ww0, p0);
        p0 = fmaf(fmaxf(acc[nt][1] + bb1, 0.0f), ww1, p0);
        p1 = fmaf(fmaxf(acc[nt][2] + bb0, 0.0f), ww0, p1);
        p1 = fmaf(fmaxf(acc[nt][3] + bb1, 0.0f), ww1, p1);
    }
    p0 += __shfl_xor_sync(0xffffffffu, p0, 1);
    p0 += __shfl_xor_sync(0xffffffffu, p0, 2);
    p1 += __shfl_xor_sync(0xffffffffu, p1, 1);
    p1 += __shfl_xor_sync(0xffffffffu, p1, 2);
    if (tig == 0) {
        float b2v = __ldg(b2);
        if (v0) outp[m0] = fmaxf(p0 + g_xw2[m0] + b2v, 0.0f);
        if (v1) outp[m1] = fmaxf(p1 + g_xw2[m1] + b2v, 0.0f);
    }
}

// ---------------- gather: agg = dinv_i*xw_i + sum dinv_s*xw_s; acat pack ------------
__global__ void __launch_bounds__(256) k_gather(
    const float* __restrict__ temporal,
    const float* __restrict__ b_gcn, int n)
{
    int gw   = (blockIdx.x * blockDim.x + threadIdx.x) >> 5;
    int lane = threadIdx.x & 31;
    if (gw >= n) return;
    int i = gw;

    float di = g_dinv[i];
    float4 acc = make_float4(0.f, 0.f, 0.f, 0.f);
    if (lane < 24) {
        float4 v = reinterpret_cast<const float4*>(g_xw)[(size_t)i * 24 + lane];
        acc.x = v.x * di; acc.y = v.y * di; acc.z = v.z * di; acc.w = v.w * di;
    }

    int start = g_row[i];
    int cnt   = g_cnt[i];
    for (int base = 0; base < cnt; base += 32) {
        int e = base + lane;
        int s = (e < cnt) ? g_csr[start + e] : 0;
        int m = min(32, cnt - base);
        int j = 0;
        for (; j + 2 <= m; j += 2) {
            int s0 = __shfl_sync(0xffffffffu, s, j);
            int s1 = __shfl_sync(0xffffffffu, s, j + 1);
            float d0 = g_dinv[s0];
            float d1 = g_dinv[s1];
            if (lane < 24) {
                float4 v0 = reinterpret_cast<const float4*>(g_xw)[(size_t)s0 * 24 + lane];
                float4 v1 = reinterpret_cast<const float4*>(g_xw)[(size_t)s1 * 24 + lane];
                acc.x = fmaf(v0.x, d0, fmaf(v1.x, d1, acc.x));
                acc.y = fmaf(v0.y, d0, fmaf(v1.y, d1, acc.y));
                acc.z = fmaf(v0.z, d0, fmaf(v1.z, d1, acc.z));
                acc.w = fmaf(v0.w, d0, fmaf(v1.w, d1, acc.w));
            }
        }
        if (j < m) {
            int s0 = __shfl_sync(0xffffffffu, s, j);
            float d0 = g_dinv[s0];
            if (lane < 24) {
                float4 v0 = reinterpret_cast<const float4*>(g_xw)[(size_t)s0 * 24 + lane];
                acc.x = fmaf(v0.x, d0, acc.x);
                acc.y = fmaf(v0.y, d0, acc.y);
                acc.z = fmaf(v0.z, d0, acc.z);
                acc.w = fmaf(v0.w, d0, acc.w);
            }
        }
    }

    if (lane < 24) {
        float4 b = reinterpret_cast<const float4*>(b_gcn)[lane];
        float4 o;
        o.x = fmaxf(fmaf(di, acc.x, b.x), 0.0f);
        o.y = fmaxf(fmaf(di, acc.y, b.y), 0.0f);
        o.z = fmaxf(fmaf(di, acc.z, b.z), 0.0f);
        o.w = fmaxf(fmaf(di, acc.w, b.w), 0.0f);
        reinterpret_cast<float4*>(g_acat)[(size_t)i * 32 + lane] = o;
    } else {
#pragma unroll
        for (int q = 0; q < 4; q++) {
            int c = 96 + (lane - 24) * 4 + q;
            float v = (c < HIDN + TEMPF) ? temporal[(size_t)i * TEMPF + (c - HIDN)] : 0.0f;
            g_acat[(size_t)i * GK + c] = v;
        }
    }
}

// ---------------- launch ----------------
extern "C" void kernel_launch(void* const* d_in, const int* in_sizes, int n_in,
                              void* d_out, int out_size) {
    const float* x        = (const float*)d_in[0];
    const int*   ei       = (const int*)  d_in[1];   // int32 (JAX x64 disabled)
    const float* temporal = (const float*)d_in[2];
    const float* W_gcn    = (const float*)d_in[3];
    const float* b_gcn    = (const float*)d_in[4];
    const float* W1       = (const float*)d_in[5];
    const float* b1       = (const float*)d_in[6];
    const float* W2       = (const float*)d_in[7];
    const float* b2       = (const float*)d_in[8];
    float*       out      = (float*)d_out;

    int N  = in_sizes[0] / NODEF;   // 50000
    int E  = in_sizes[1] / 2;       // 800000
    int nb = (N + 255) / 256;       // 196
    int ng = (N + 127) / 128;       // 391 HMMA tiles
    int ne = (E + 255) / 256;       // 3125 count/fill blocks
    const int KS2 = HIDN + TEMPF;   // 106

    k_zero_cnt <<<nb, 256>>>(N);
    k_packbf   <<<12, 256>>>(W_gcn, 128, 0);
    k_packbf   <<<12, 256>>>(W1,   KS2, 1);

    // count (edges) ∥ GEMM1 raw (+xw2) in one launch
    k_front    <<<ng + ne, 256>>>(ei, E, x, W2, N, ng);

    k_scan_blk <<<nb, 256>>>(N);
    k_scan_add <<<nb, 256>>>(N);
    k_fill     <<<ne, 256>>>(ei, E);

    k_gather   <<<(N * 32 + 255) / 256, 256>>>(temporal, b_gcn, N);   // g_acat

    k_mma1     <<<ng, 256>>>(b1, W2, b2, out, N);                     // fused final
}